// round 6
// baseline (speedup 1.0000x reference)
#include <cuda_runtime.h>
#include <cuda_fp16.h>

#define NMAX 50000
#define EMAX 800000

// ---------------- scratch ----------------
__device__ __half  g_h1h[NMAX * 64];   // layer-1 features, fp16
__device__ float   g_h2[NMAX * 64];    // post-relu hidden (gemm2 input), fp32
__device__ float2  g_as1[NMAX];
__device__ float2  g_ad1[NMAX];
__device__ __half  g_h3h[NMAX * 32];   // interleaved [mu(16) | ls(16)], fp16
__device__ float2  g_a2s[NMAX];
__device__ float2  g_a2d[NMAX];
__device__ int     g_deg[NMAX];
__device__ int     g_rowptr[NMAX];
__device__ int     g_cursor[NMAX];
__device__ int     g_col[EMAX];
__device__ int     g_bsum[64];
__device__ int     g_e64;

__device__ __forceinline__ float leakyf(float x) { return x > 0.f ? x : 0.2f * x; }

__device__ __forceinline__ int load_edge(const void* ei, long long idx) {
    if (g_e64) return (int)((const long long*)ei)[idx];
    return ((const int*)ei)[idx];
}

// packed f32x2 helpers (sm_100+)
__device__ __forceinline__ unsigned long long dup_f32x2(float a) {
    unsigned long long r;
    asm("mov.b64 %0, {%1, %1};" : "=l"(r) : "f"(a));
    return r;
}
__device__ __forceinline__ void fma_f32x2(unsigned long long& d,
                                          unsigned long long a, unsigned long long b) {
    asm("fma.rn.f32x2 %0, %1, %2, %0;" : "+l"(d) : "l"(a), "l"(b));
}
__device__ __forceinline__ float2 unpk_f32x2(unsigned long long v) {
    float lo, hi;
    asm("mov.b64 {%0, %1}, %2;" : "=f"(lo), "=f"(hi) : "l"(v));
    return make_float2(lo, hi);
}

// ---------------- init: zero deg + dtype detection ----------------
__global__ void k_init(const void* ei, int E, int N) {
    int i = blockIdx.x * blockDim.x + threadIdx.x;
    if (i < N) g_deg[i] = 0;
    if (i == 0) {
        const long long* p = (const long long*)ei;
        int ok = 1;
        int cnt = E < 256 ? E : 256;
        for (int k = 0; k < cnt; k++) {
            long long v = p[k];
            if (v < 0 || v >= (long long)N) { ok = 0; break; }
        }
        g_e64 = ok;
    }
}

__global__ void k_hist(const void* ei, int E) {
    int i = blockIdx.x * blockDim.x + threadIdx.x;
    if (i < E) {
        int d = load_edge(ei, (long long)E + i);
        atomicAdd(&g_deg[d], 1);
    }
}

// ---------------- scan phase 1 ----------------
__global__ void k_scan1(int N) {
    __shared__ int warp_sums[32];
    int i = blockIdx.x * 1024 + threadIdx.x;
    int lane = threadIdx.x & 31, wid = threadIdx.x >> 5;
    int v = (i < N) ? g_deg[i] : 0;
    int incl = v;
#pragma unroll
    for (int o = 1; o < 32; o <<= 1) {
        int t = __shfl_up_sync(0xffffffffu, incl, o);
        if (lane >= o) incl += t;
    }
    if (lane == 31) warp_sums[wid] = incl;
    __syncthreads();
    if (wid == 0) {
        int s = warp_sums[lane];
        int si = s;
#pragma unroll
        for (int o = 1; o < 32; o <<= 1) {
            int t = __shfl_up_sync(0xffffffffu, si, o);
            if (lane >= o) si += t;
        }
        warp_sums[lane] = si - s;
        if (lane == 31) g_bsum[blockIdx.x] = si;
    }
    __syncthreads();
    if (i < N) g_rowptr[i] = incl - v + warp_sums[wid];
}

// ---------------- scan phase 2+3 fused ----------------
__global__ void k_scan23(int N, int nb) {
    __shared__ int s_ofs;
    int b = blockIdx.x;
    if (threadIdx.x < 32) {
        int lane = threadIdx.x;
        int p = 0;
        if (lane < b && lane < nb)           p += g_bsum[lane];
        if (lane + 32 < b && lane + 32 < nb) p += g_bsum[lane + 32];
#pragma unroll
        for (int o = 16; o > 0; o >>= 1) p += __shfl_down_sync(0xffffffffu, p, o);
        if (lane == 0) s_ofs = p;
    }
    __syncthreads();
    int i = b * 1024 + threadIdx.x;
    if (i < N) {
        int r = g_rowptr[i] + s_ofs;
        g_rowptr[i] = r;
        g_cursor[i] = r;
    }
}

// ---------------- GEMM1: h1 = x @ W1 (f32x2), half output; att scalars ----------------
__global__ __launch_bounds__(256) void k_gemm1(
    const float* __restrict__ x, const float* __restrict__ W,
    const float* __restrict__ att_s, const float* __restrict__ att_d, int M)
{
    __shared__ float As[32][68];
    __shared__ float Bs[32][64];
    __shared__ float s_s[64][2];
    __shared__ float s_d[64][2];
    int tid = threadIdx.x;
    int tx = tid & 15, ty = tid >> 4;
    int m0 = blockIdx.x * 64;

    unsigned long long acc[4][2];   // [row][col-pair]: (c0,c1),(c2,c3)
#pragma unroll
    for (int i = 0; i < 4; i++) { acc[i][0] = 0ull; acc[i][1] = 0ull; }

    int arow = tid >> 2;     // 0..63
    int ac4  = tid & 3;      // first of two float4 k-slots
    for (int k0 = 0; k0 < 128; k0 += 32) {
#pragma unroll
        for (int h = 0; h < 2; h++) {
            int kslot = ac4 + h * 4;           // 0..7
            float4 av = make_float4(0.f, 0.f, 0.f, 0.f);
            int gm = m0 + arow;
            if (gm < M) av = *reinterpret_cast<const float4*>(x + (size_t)gm * 128 + k0 + kslot * 4);
            As[kslot * 4 + 0][arow] = av.x;
            As[kslot * 4 + 1][arow] = av.y;
            As[kslot * 4 + 2][arow] = av.z;
            As[kslot * 4 + 3][arow] = av.w;
        }
#pragma unroll
        for (int h = 0; h < 2; h++) {
            int kk = (tid >> 4) + h * 16;
            *reinterpret_cast<float4*>(&Bs[kk][(tid & 15) * 4]) =
                *reinterpret_cast<const float4*>(W + (size_t)(k0 + kk) * 64 + (tid & 15) * 4);
        }
        __syncthreads();
#pragma unroll
        for (int k = 0; k < 32; k++) {
            float4 a = *reinterpret_cast<float4*>(&As[k][ty * 4]);
            ulonglong2 b = *reinterpret_cast<ulonglong2*>(&Bs[k][tx * 4]);
            unsigned long long a0 = dup_f32x2(a.x), a1 = dup_f32x2(a.y),
                               a2 = dup_f32x2(a.z), a3 = dup_f32x2(a.w);
            fma_f32x2(acc[0][0], a0, b.x); fma_f32x2(acc[0][1], a0, b.y);
            fma_f32x2(acc[1][0], a1, b.x); fma_f32x2(acc[1][1], a1, b.y);
            fma_f32x2(acc[2][0], a2, b.x); fma_f32x2(acc[2][1], a2, b.y);
            fma_f32x2(acc[3][0], a3, b.x); fma_f32x2(acc[3][1], a3, b.y);
        }
        __syncthreads();
    }

    if (tid < 128) { s_s[tid >> 1][tid & 1] = 0.f; s_d[tid >> 1][tid & 1] = 0.f; }
    __syncthreads();

    int head = tx >> 3;
    float asv[4], adv[4];
#pragma unroll
    for (int j = 0; j < 4; j++) { asv[j] = att_s[tx * 4 + j]; adv[j] = att_d[tx * 4 + j]; }
#pragma unroll
    for (int i = 0; i < 4; i++) {
        int r = ty * 4 + i;
        int gm = m0 + r;
        float2 c01 = unpk_f32x2(acc[i][0]);
        float2 c23 = unpk_f32x2(acc[i][1]);
        float c[4] = {c01.x, c01.y, c23.x, c23.y};
        float ps = 0.f, pd = 0.f;
#pragma unroll
        for (int j = 0; j < 4; j++) { ps += c[j] * asv[j]; pd += c[j] * adv[j]; }
        atomicAdd(&s_s[r][head], ps);
        atomicAdd(&s_d[r][head], pd);
        if (gm < M) {
            __half2 h01 = __floats2half2_rn(c[0], c[1]);
            __half2 h23 = __floats2half2_rn(c[2], c[3]);
            uint2 st;
            st.x = *reinterpret_cast<unsigned int*>(&h01);
            st.y = *reinterpret_cast<unsigned int*>(&h23);
            *reinterpret_cast<uint2*>(&g_h1h[(size_t)gm * 64 + tx * 4]) = st;
        }
    }
    __syncthreads();
    if (tid < 64) {
        int gm = m0 + tid;
        if (gm < M) {
            g_as1[gm] = make_float2(s_s[tid][0], s_s[tid][1]);
            g_ad1[gm] = make_float2(s_d[tid][0], s_d[tid][1]);
        }
    }
}

// ---------------- scatter: CSR column fill ----------------
__global__ void k_scatter(const void* ei, int E) {
    int i = blockIdx.x * blockDim.x + threadIdx.x;
    if (i >= E) return;
    int s = load_edge(ei, i);
    int d = load_edge(ei, (long long)E + i);
    int pos = atomicAdd(&g_cursor[d], 1);
    g_col[pos] = s;
}

// ---------------- layer-1 agg: warp/node, half2 gather, lane = channels 2l,2l+1 ----------------
__global__ __launch_bounds__(256) void k_agg1(const float* __restrict__ b1, int N) {
    __shared__ float4 stage[8][32];
    int n = (blockIdx.x * blockDim.x + threadIdx.x) >> 5;
    int lane = threadIdx.x & 31;
    int w = threadIdx.x >> 5;
    if (n >= N) return;
    int start = g_rowptr[n];
    int deg = g_deg[n];
    float2 ad = g_ad1[n];
    float2 as = g_as1[n];
    float ws0 = __expf(leakyf(as.x + ad.x));
    float ws1 = __expf(leakyf(as.y + ad.y));
    bool head1 = lane >= 16;
    float wself = head1 ? ws1 : ws0;
    float den0 = ws0, den1 = ws1;
    float2 hs = __half22float2(*reinterpret_cast<const __half2*>(&g_h1h[(size_t)n * 64 + 2 * lane]));
    float acc0 = wself * hs.x, acc1 = wself * hs.y;
    for (int base = 0; base < deg; base += 32) {
        int i = base + lane;
        float4 st = make_float4(0.f, 0.f, 0.f, 0.f);
        if (i < deg) {
            int s = g_col[start + i];
            float2 a = g_as1[s];
            st.x = __int_as_float(s);
            st.y = __expf(leakyf(a.x + ad.x));
            st.z = __expf(leakyf(a.y + ad.y));
        }
        stage[w][lane] = st;
        __syncwarp();
        int cnt = min(32, deg - base);
#pragma unroll 4
        for (int j = 0; j < cnt; j++) {
            float4 v = stage[w][j];
            int sj = __float_as_int(v.x);
            den0 += v.y; den1 += v.z;
            float ww = head1 ? v.z : v.y;
            float2 hf = __half22float2(*reinterpret_cast<const __half2*>(&g_h1h[(size_t)sj * 64 + 2 * lane]));
            acc0 += ww * hf.x;
            acc1 += ww * hf.y;
        }
        __syncwarp();
    }
    float inv = 1.f / ((head1 ? den1 : den0) + 1e-16f);
    float v0 = acc0 * inv + b1[2 * lane];
    float v1 = acc1 * inv + b1[2 * lane + 1];
    *reinterpret_cast<float2*>(&g_h2[(size_t)n * 64 + 2 * lane]) =
        make_float2(v0 > 0.f ? v0 : 0.f, v1 > 0.f ? v1 : 0.f);
}

// ---------------- GEMM2: h3 = h2 @ [W_mu | W_ls] interleaved (half out); att scalars ----------------
__global__ __launch_bounds__(256) void k_gemm2(
    const float* __restrict__ Wmu, const float* __restrict__ Wls,
    const float* __restrict__ asmu, const float* __restrict__ admu,
    const float* __restrict__ asls, const float* __restrict__ adls, int M)
{
    __shared__ float As[16][132];
    __shared__ float Bs[16][32];
    __shared__ float s_ms[128], s_md[128], s_lsm[128], s_ldm[128];
    int tid = threadIdx.x;
    int tx = tid & 7, ty = tid >> 3;
    int m0 = blockIdx.x * 128;
    float acc[4][4];
#pragma unroll
    for (int i = 0; i < 4; i++)
#pragma unroll
        for (int j = 0; j < 4; j++) acc[i][j] = 0.f;

    int arow = tid >> 2;
    int ac4  = tid & 3;
    for (int k0 = 0; k0 < 64; k0 += 16) {
#pragma unroll
        for (int h = 0; h < 2; h++) {
            int r = arow + h * 64;
            int gm = m0 + r;
            float4 av = make_float4(0.f, 0.f, 0.f, 0.f);
            if (gm < M) av = *reinterpret_cast<const float4*>(&g_h2[(size_t)gm * 64 + k0 + ac4 * 4]);
            As[ac4 * 4 + 0][r] = av.x;
            As[ac4 * 4 + 1][r] = av.y;
            As[ac4 * 4 + 2][r] = av.z;
            As[ac4 * 4 + 3][r] = av.w;
        }
#pragma unroll
        for (int h = 0; h < 2; h++) {
            int idx = tid + h * 256;
            int kk = idx >> 5, c = idx & 31;
            Bs[kk][c] = (c < 16) ? Wmu[(size_t)(k0 + kk) * 16 + c]
                                 : Wls[(size_t)(k0 + kk) * 16 + (c - 16)];
        }
        __syncthreads();
#pragma unroll
        for (int k = 0; k < 16; k++) {
            float4 a = *reinterpret_cast<float4*>(&As[k][ty * 4]);
            float4 b = *reinterpret_cast<float4*>(&Bs[k][tx * 4]);
            float a4[4] = {a.x, a.y, a.z, a.w};
            float b4[4] = {b.x, b.y, b.z, b.w};
#pragma unroll
            for (int i = 0; i < 4; i++)
#pragma unroll
                for (int j = 0; j < 4; j++) acc[i][j] += a4[i] * b4[j];
        }
        __syncthreads();
    }

    if (tid < 128) { s_ms[tid] = 0.f; s_md[tid] = 0.f; s_lsm[tid] = 0.f; s_ldm[tid] = 0.f; }
    __syncthreads();

    bool is_mu = (tx < 4);
    int cb = (tx & 3) * 4;
    const float* ap_s = is_mu ? asmu : asls;
    const float* ap_d = is_mu ? admu : adls;
    float vs[4], vd[4];
#pragma unroll
    for (int j = 0; j < 4; j++) { vs[j] = ap_s[cb + j]; vd[j] = ap_d[cb + j]; }
    float* s_ps = is_mu ? s_ms : s_lsm;
    float* s_pd = is_mu ? s_md : s_ldm;
    int col0 = (is_mu ? 0 : 16) + cb;
#pragma unroll
    for (int i = 0; i < 4; i++) {
        int r = ty * 4 + i;
        int gm = m0 + r;
        float ps = 0.f, pd = 0.f;
#pragma unroll
        for (int j = 0; j < 4; j++) { ps += acc[i][j] * vs[j]; pd += acc[i][j] * vd[j]; }
        atomicAdd(&s_ps[r], ps);
        atomicAdd(&s_pd[r], pd);
        if (gm < M) {
            __half2 h01 = __floats2half2_rn(acc[i][0], acc[i][1]);
            __half2 h23 = __floats2half2_rn(acc[i][2], acc[i][3]);
            uint2 st;
            st.x = *reinterpret_cast<unsigned int*>(&h01);
            st.y = *reinterpret_cast<unsigned int*>(&h23);
            *reinterpret_cast<uint2*>(&g_h3h[(size_t)gm * 32 + col0]) = st;
        }
    }
    __syncthreads();
    if (tid < 128) {
        int gm = m0 + tid;
        if (gm < M) {
            g_a2s[gm] = make_float2(s_ms[tid], s_lsm[tid]);
            g_a2d[gm] = make_float2(s_md[tid], s_ldm[tid]);
        }
    }
}

// ---------------- layer-2 agg: warp/node, half gather ----------------
__global__ __launch_bounds__(256) void k_agg2(
    const float* __restrict__ bmu, const float* __restrict__ bls,
    float* __restrict__ out, int N)
{
    __shared__ float4 stage[8][32];
    int n = (blockIdx.x * blockDim.x + threadIdx.x) >> 5;
    int lane = threadIdx.x & 31;
    int w = threadIdx.x >> 5;
    if (n >= N) return;
    int start = g_rowptr[n];
    int deg = g_deg[n];
    float2 ad = g_a2d[n];
    float2 as = g_a2s[n];
    float wsm = __expf(leakyf(as.x + ad.x));
    float wsl = __expf(leakyf(as.y + ad.y));
    bool is_mu = lane < 16;
    int c = lane & 15;
    float wself = is_mu ? wsm : wsl;
    float den = wself;
    float acc = wself * __half2float(g_h3h[(size_t)n * 32 + lane]);
    for (int base = 0; base < deg; base += 32) {
        int i = base + lane;
        float4 st = make_float4(0.f, 0.f, 0.f, 0.f);
        if (i < deg) {
            int s = g_col[start + i];
            float2 a = g_a2s[s];
            st.x = __int_as_float(s);
            st.y = __expf(leakyf(a.x + ad.x));
            st.z = __expf(leakyf(a.y + ad.y));
        }
        stage[w][lane] = st;
        __syncwarp();
        int cnt = min(32, deg - base);
#pragma unroll 4
        for (int j = 0; j < cnt; j++) {
            float4 v = stage[w][j];
            int sj = __float_as_int(v.x);
            float ww = is_mu ? v.y : v.z;
            den += ww;
            acc += ww * __half2float(g_h3h[(size_t)sj * 32 + lane]);
        }
        __syncwarp();
    }
    float res = acc * (1.f / (den + 1e-16f)) + (is_mu ? bmu[c] : bls[c]);
    if (is_mu) out[(size_t)n * 16 + c] = res;
    else       out[(size_t)N * 16 + (size_t)n * 16 + c] = res;
}

// ---------------- launch ----------------
extern "C" void kernel_launch(void* const* d_in, const int* in_sizes, int n_in,
                              void* d_out, int out_size) {
    const float* x    = (const float*)d_in[0];
    const void*  ei   = d_in[1];
    const float* W1   = (const float*)d_in[2];
    const float* as1  = (const float*)d_in[3];
    const float* ad1  = (const float*)d_in[4];
    const float* b1   = (const float*)d_in[5];
    const float* Wmu  = (const float*)d_in[6];
    const float* asmu = (const float*)d_in[7];
    const float* admu = (const float*)d_in[8];
    const float* bmu  = (const float*)d_in[9];
    const float* Wls  = (const float*)d_in[10];
    const float* asls = (const float*)d_in[11];
    const float* adls = (const float*)d_in[12];
    const float* bls  = (const float*)d_in[13];
    int N = in_sizes[0] / 128;
    int E = in_sizes[1] / 2;
    float* out = (float*)d_out;

    static cudaStream_t s2 = nullptr;
    static cudaEvent_t evF = nullptr, evJ = nullptr;
    if (s2 == nullptr) {
        cudaStreamCreateWithFlags(&s2, cudaStreamNonBlocking);
        cudaEventCreateWithFlags(&evF, cudaEventDisableTiming);
        cudaEventCreateWithFlags(&evJ, cudaEventDisableTiming);
    }

    const int TB = 256;
    int nb = (N + 1023) / 1024;

    cudaEventRecord(evF, 0);
    cudaStreamWaitEvent(s2, evF, 0);

    k_init<<<(N + TB - 1) / TB, TB>>>(ei, E, N);               // idx0
    k_hist<<<(E + 511) / 512, 512>>>(ei, E);                   // idx1
    k_scan1<<<nb, 1024>>>(N);                                  // idx2
    k_gemm1<<<(N + 63) / 64, 256, 0, s2>>>(x, W1, as1, ad1, N);// idx3 (profiled)
    k_scan23<<<nb, 1024>>>(N, nb);                             // idx4
    k_scatter<<<(E + 511) / 512, 512>>>(ei, E);                // idx5

    cudaEventRecord(evJ, s2);
    cudaStreamWaitEvent(0, evJ, 0);

    k_agg1<<<(N * 32 + TB - 1) / TB, TB>>>(b1, N);             // idx6
    k_gemm2<<<(N + 127) / 128, 256>>>(Wmu, Wls, asmu, admu, asls, adls, N); // idx7
    k_agg2<<<(N * 32 + TB - 1) / TB, TB>>>(bmu, bls, out, N);  // idx8
}

// round 7
// speedup vs baseline: 1.0229x; 1.0229x over previous
#include <cuda_runtime.h>
#include <cuda_fp16.h>

#define NMAX 50000
#define EMAX 800000

// ---------------- scratch ----------------
__device__ __half  g_h1h[NMAX * 64];   // layer-1 features, fp16
__device__ float   g_h2[NMAX * 64];    // post-relu hidden (gemm2 input), fp32
__device__ float2  g_as1[NMAX];
__device__ float2  g_ad1[NMAX];
__device__ __half  g_h3h[NMAX * 32];   // interleaved [mu(16) | ls(16)], fp16
__device__ float2  g_a2s[NMAX];
__device__ float2  g_a2d[NMAX];
__device__ int     g_deg[NMAX];
__device__ int     g_rowptr[NMAX];
__device__ int     g_cursor[NMAX];
__device__ int     g_col[EMAX];
__device__ int     g_bsum[64];
__device__ int     g_e64;

__device__ __forceinline__ float leakyf(float x) { return x > 0.f ? x : 0.2f * x; }

__device__ __forceinline__ int load_edge(const void* ei, long long idx) {
    if (g_e64) return (int)((const long long*)ei)[idx];
    return ((const int*)ei)[idx];
}

// packed f32x2 helpers (sm_100+)
__device__ __forceinline__ unsigned long long dup_f32x2(float a) {
    unsigned long long r;
    asm("mov.b64 %0, {%1, %1};" : "=l"(r) : "f"(a));
    return r;
}
__device__ __forceinline__ void fma_f32x2(unsigned long long& d,
                                          unsigned long long a, unsigned long long b) {
    asm("fma.rn.f32x2 %0, %1, %2, %0;" : "+l"(d) : "l"(a), "l"(b));
}
__device__ __forceinline__ float2 unpk_f32x2(unsigned long long v) {
    float lo, hi;
    asm("mov.b64 {%0, %1}, %2;" : "=f"(lo), "=f"(hi) : "l"(v));
    return make_float2(lo, hi);
}

// ---------------- init: zero deg + dtype detection ----------------
__global__ void k_init(const void* ei, int E, int N) {
    int i = blockIdx.x * blockDim.x + threadIdx.x;
    if (i < N) g_deg[i] = 0;
    if (i == 0) {
        const long long* p = (const long long*)ei;
        int ok = 1;
        int cnt = E < 256 ? E : 256;
        for (int k = 0; k < cnt; k++) {
            long long v = p[k];
            if (v < 0 || v >= (long long)N) { ok = 0; break; }
        }
        g_e64 = ok;
    }
}

__global__ void k_hist(const void* ei, int E) {
    int i = blockIdx.x * blockDim.x + threadIdx.x;
    if (i < E) {
        int d = load_edge(ei, (long long)E + i);
        atomicAdd(&g_deg[d], 1);
    }
}

// ---------------- scan phase 1 ----------------
__global__ void k_scan1(int N) {
    __shared__ int warp_sums[32];
    int i = blockIdx.x * 1024 + threadIdx.x;
    int lane = threadIdx.x & 31, wid = threadIdx.x >> 5;
    int v = (i < N) ? g_deg[i] : 0;
    int incl = v;
#pragma unroll
    for (int o = 1; o < 32; o <<= 1) {
        int t = __shfl_up_sync(0xffffffffu, incl, o);
        if (lane >= o) incl += t;
    }
    if (lane == 31) warp_sums[wid] = incl;
    __syncthreads();
    if (wid == 0) {
        int s = warp_sums[lane];
        int si = s;
#pragma unroll
        for (int o = 1; o < 32; o <<= 1) {
            int t = __shfl_up_sync(0xffffffffu, si, o);
            if (lane >= o) si += t;
        }
        warp_sums[lane] = si - s;
        if (lane == 31) g_bsum[blockIdx.x] = si;
    }
    __syncthreads();
    if (i < N) g_rowptr[i] = incl - v + warp_sums[wid];
}

// ---------------- scan phase 2+3 fused ----------------
__global__ void k_scan23(int N, int nb) {
    __shared__ int s_ofs;
    int b = blockIdx.x;
    if (threadIdx.x < 32) {
        int lane = threadIdx.x;
        int p = 0;
        if (lane < b && lane < nb)           p += g_bsum[lane];
        if (lane + 32 < b && lane + 32 < nb) p += g_bsum[lane + 32];
#pragma unroll
        for (int o = 16; o > 0; o >>= 1) p += __shfl_down_sync(0xffffffffu, p, o);
        if (lane == 0) s_ofs = p;
    }
    __syncthreads();
    int i = b * 1024 + threadIdx.x;
    if (i < N) {
        int r = g_rowptr[i] + s_ofs;
        g_rowptr[i] = r;
        g_cursor[i] = r;
    }
}

// ---------------- GEMM1: 128x64 tile, 8x4 per thread, f32x2 FFMA ----------------
__global__ __launch_bounds__(256) void k_gemm1(
    const float* __restrict__ x, const float* __restrict__ W,
    const float* __restrict__ att_s, const float* __restrict__ att_d, int M)
{
    __shared__ float As[32][132];     // [k][row 0..127]
    __shared__ float Bs[32][64];      // [k][col]
    __shared__ float s_s[128][2];
    __shared__ float s_d[128][2];
    int tid = threadIdx.x;
    int tx = tid & 15;                // 4-col group
    int ty = tid >> 4;                // 8-row group
    int m0 = blockIdx.x * 128;

    unsigned long long acc[8][2];     // [row][col-pair]
#pragma unroll
    for (int i = 0; i < 8; i++) { acc[i][0] = 0ull; acc[i][1] = 0ull; }

    int lrow  = tid >> 1;             // 0..127 : A-load row
    int lcb   = (tid & 1) * 4;        // 0 or 4 : first float4 slot of 8
    for (int k0 = 0; k0 < 128; k0 += 32) {
        int gm = m0 + lrow;
#pragma unroll
        for (int c = 0; c < 4; c++) {
            int kslot = lcb + c;      // 0..7
            float4 av = make_float4(0.f, 0.f, 0.f, 0.f);
            if (gm < M) av = *reinterpret_cast<const float4*>(x + (size_t)gm * 128 + k0 + kslot * 4);
            As[kslot * 4 + 0][lrow] = av.x;
            As[kslot * 4 + 1][lrow] = av.y;
            As[kslot * 4 + 2][lrow] = av.z;
            As[kslot * 4 + 3][lrow] = av.w;
        }
#pragma unroll
        for (int h = 0; h < 2; h++) {
            int idx = tid + h * 256;  // 0..511
            int kk = idx >> 4;        // 0..31
            int cc = idx & 15;        // float4 col group
            *reinterpret_cast<float4*>(&Bs[kk][cc * 4]) =
                *reinterpret_cast<const float4*>(W + (size_t)(k0 + kk) * 64 + cc * 4);
        }
        __syncthreads();
#pragma unroll
        for (int k = 0; k < 32; k++) {
            float4 a0 = *reinterpret_cast<float4*>(&As[k][ty * 8]);
            float4 a1 = *reinterpret_cast<float4*>(&As[k][ty * 8 + 4]);
            ulonglong2 b = *reinterpret_cast<ulonglong2*>(&Bs[k][tx * 4]);
            unsigned long long d0 = dup_f32x2(a0.x), d1 = dup_f32x2(a0.y),
                               d2 = dup_f32x2(a0.z), d3 = dup_f32x2(a0.w),
                               d4 = dup_f32x2(a1.x), d5 = dup_f32x2(a1.y),
                               d6 = dup_f32x2(a1.z), d7 = dup_f32x2(a1.w);
            fma_f32x2(acc[0][0], d0, b.x); fma_f32x2(acc[0][1], d0, b.y);
            fma_f32x2(acc[1][0], d1, b.x); fma_f32x2(acc[1][1], d1, b.y);
            fma_f32x2(acc[2][0], d2, b.x); fma_f32x2(acc[2][1], d2, b.y);
            fma_f32x2(acc[3][0], d3, b.x); fma_f32x2(acc[3][1], d3, b.y);
            fma_f32x2(acc[4][0], d4, b.x); fma_f32x2(acc[4][1], d4, b.y);
            fma_f32x2(acc[5][0], d5, b.x); fma_f32x2(acc[5][1], d5, b.y);
            fma_f32x2(acc[6][0], d6, b.x); fma_f32x2(acc[6][1], d6, b.y);
            fma_f32x2(acc[7][0], d7, b.x); fma_f32x2(acc[7][1], d7, b.y);
        }
        __syncthreads();
    }

    { s_s[tid >> 1][tid & 1] = 0.f; s_d[tid >> 1][tid & 1] = 0.f; }
    __syncthreads();

    int head = tx >> 3;               // cols [0,32) head0, [32,64) head1
    float asv[4], adv[4];
#pragma unroll
    for (int j = 0; j < 4; j++) { asv[j] = att_s[tx * 4 + j]; adv[j] = att_d[tx * 4 + j]; }
#pragma unroll
    for (int i = 0; i < 8; i++) {
        int r = ty * 8 + i;
        int gm = m0 + r;
        float2 c01 = unpk_f32x2(acc[i][0]);
        float2 c23 = unpk_f32x2(acc[i][1]);
        float c[4] = {c01.x, c01.y, c23.x, c23.y};
        float ps = 0.f, pd = 0.f;
#pragma unroll
        for (int j = 0; j < 4; j++) { ps += c[j] * asv[j]; pd += c[j] * adv[j]; }
        atomicAdd(&s_s[r][head], ps);
        atomicAdd(&s_d[r][head], pd);
        if (gm < M) {
            __half2 h01 = __floats2half2_rn(c[0], c[1]);
            __half2 h23 = __floats2half2_rn(c[2], c[3]);
            uint2 st;
            st.x = *reinterpret_cast<unsigned int*>(&h01);
            st.y = *reinterpret_cast<unsigned int*>(&h23);
            *reinterpret_cast<uint2*>(&g_h1h[(size_t)gm * 64 + tx * 4]) = st;
        }
    }
    __syncthreads();
    if (tid < 128) {
        int gm = m0 + tid;
        if (gm < M) {
            g_as1[gm] = make_float2(s_s[tid][0], s_s[tid][1]);
            g_ad1[gm] = make_float2(s_d[tid][0], s_d[tid][1]);
        }
    }
}

// ---------------- scatter: CSR column fill ----------------
__global__ void k_scatter(const void* ei, int E) {
    int i = blockIdx.x * blockDim.x + threadIdx.x;
    if (i >= E) return;
    int s = load_edge(ei, i);
    int d = load_edge(ei, (long long)E + i);
    int pos = atomicAdd(&g_cursor[d], 1);
    g_col[pos] = s;
}

// ---------------- layer-1 agg: warp/node, half2 gather, lane = channels 2l,2l+1 ----------------
__global__ __launch_bounds__(256) void k_agg1(const float* __restrict__ b1, int N) {
    __shared__ float4 stage[8][32];
    int n = (blockIdx.x * blockDim.x + threadIdx.x) >> 5;
    int lane = threadIdx.x & 31;
    int w = threadIdx.x >> 5;
    if (n >= N) return;
    int start = g_rowptr[n];
    int deg = g_deg[n];
    float2 ad = g_ad1[n];
    float2 as = g_as1[n];
    float ws0 = __expf(leakyf(as.x + ad.x));
    float ws1 = __expf(leakyf(as.y + ad.y));
    bool head1 = lane >= 16;
    float wself = head1 ? ws1 : ws0;
    float den0 = ws0, den1 = ws1;
    float2 hs = __half22float2(*reinterpret_cast<const __half2*>(&g_h1h[(size_t)n * 64 + 2 * lane]));
    float acc0 = wself * hs.x, acc1 = wself * hs.y;
    for (int base = 0; base < deg; base += 32) {
        int i = base + lane;
        float4 st = make_float4(0.f, 0.f, 0.f, 0.f);
        if (i < deg) {
            int s = g_col[start + i];
            float2 a = g_as1[s];
            st.x = __int_as_float(s);
            st.y = __expf(leakyf(a.x + ad.x));
            st.z = __expf(leakyf(a.y + ad.y));
        }
        stage[w][lane] = st;
        __syncwarp();
        int cnt = min(32, deg - base);
#pragma unroll 4
        for (int j = 0; j < cnt; j++) {
            float4 v = stage[w][j];
            int sj = __float_as_int(v.x);
            den0 += v.y; den1 += v.z;
            float ww = head1 ? v.z : v.y;
            float2 hf = __half22float2(*reinterpret_cast<const __half2*>(&g_h1h[(size_t)sj * 64 + 2 * lane]));
            acc0 += ww * hf.x;
            acc1 += ww * hf.y;
        }
        __syncwarp();
    }
    float inv = 1.f / ((head1 ? den1 : den0) + 1e-16f);
    float v0 = acc0 * inv + b1[2 * lane];
    float v1 = acc1 * inv + b1[2 * lane + 1];
    *reinterpret_cast<float2*>(&g_h2[(size_t)n * 64 + 2 * lane]) =
        make_float2(v0 > 0.f ? v0 : 0.f, v1 > 0.f ? v1 : 0.f);
}

// ---------------- GEMM2: h3 = h2 @ [W_mu | W_ls] interleaved (half out); att scalars ----------------
__global__ __launch_bounds__(256) void k_gemm2(
    const float* __restrict__ Wmu, const float* __restrict__ Wls,
    const float* __restrict__ asmu, const float* __restrict__ admu,
    const float* __restrict__ asls, const float* __restrict__ adls, int M)
{
    __shared__ float As[16][132];
    __shared__ float Bs[16][32];
    __shared__ float s_ms[128], s_md[128], s_lsm[128], s_ldm[128];
    int tid = threadIdx.x;
    int tx = tid & 7, ty = tid >> 3;
    int m0 = blockIdx.x * 128;
    float acc[4][4];
#pragma unroll
    for (int i = 0; i < 4; i++)
#pragma unroll
        for (int j = 0; j < 4; j++) acc[i][j] = 0.f;

    int arow = tid >> 2;
    int ac4  = tid & 3;
    for (int k0 = 0; k0 < 64; k0 += 16) {
#pragma unroll
        for (int h = 0; h < 2; h++) {
            int r = arow + h * 64;
            int gm = m0 + r;
            float4 av = make_float4(0.f, 0.f, 0.f, 0.f);
            if (gm < M) av = *reinterpret_cast<const float4*>(&g_h2[(size_t)gm * 64 + k0 + ac4 * 4]);
            As[ac4 * 4 + 0][r] = av.x;
            As[ac4 * 4 + 1][r] = av.y;
            As[ac4 * 4 + 2][r] = av.z;
            As[ac4 * 4 + 3][r] = av.w;
        }
#pragma unroll
        for (int h = 0; h < 2; h++) {
            int idx = tid + h * 256;
            int kk = idx >> 5, c = idx & 31;
            Bs[kk][c] = (c < 16) ? Wmu[(size_t)(k0 + kk) * 16 + c]
                                 : Wls[(size_t)(k0 + kk) * 16 + (c - 16)];
        }
        __syncthreads();
#pragma unroll
        for (int k = 0; k < 16; k++) {
            float4 a = *reinterpret_cast<float4*>(&As[k][ty * 4]);
            float4 b = *reinterpret_cast<float4*>(&Bs[k][tx * 4]);
            float a4[4] = {a.x, a.y, a.z, a.w};
            float b4[4] = {b.x, b.y, b.z, b.w};
#pragma unroll
            for (int i = 0; i < 4; i++)
#pragma unroll
                for (int j = 0; j < 4; j++) acc[i][j] += a4[i] * b4[j];
        }
        __syncthreads();
    }

    if (tid < 128) { s_ms[tid] = 0.f; s_md[tid] = 0.f; s_lsm[tid] = 0.f; s_ldm[tid] = 0.f; }
    __syncthreads();

    bool is_mu = (tx < 4);
    int cb = (tx & 3) * 4;
    const float* ap_s = is_mu ? asmu : asls;
    const float* ap_d = is_mu ? admu : adls;
    float vs[4], vd[4];
#pragma unroll
    for (int j = 0; j < 4; j++) { vs[j] = ap_s[cb + j]; vd[j] = ap_d[cb + j]; }
    float* s_ps = is_mu ? s_ms : s_lsm;
    float* s_pd = is_mu ? s_md : s_ldm;
    int col0 = (is_mu ? 0 : 16) + cb;
#pragma unroll
    for (int i = 0; i < 4; i++) {
        int r = ty * 4 + i;
        int gm = m0 + r;
        float ps = 0.f, pd = 0.f;
#pragma unroll
        for (int j = 0; j < 4; j++) { ps += acc[i][j] * vs[j]; pd += acc[i][j] * vd[j]; }
        atomicAdd(&s_ps[r], ps);
        atomicAdd(&s_pd[r], pd);
        if (gm < M) {
            __half2 h01 = __floats2half2_rn(acc[i][0], acc[i][1]);
            __half2 h23 = __floats2half2_rn(acc[i][2], acc[i][3]);
            uint2 st;
            st.x = *reinterpret_cast<unsigned int*>(&h01);
            st.y = *reinterpret_cast<unsigned int*>(&h23);
            *reinterpret_cast<uint2*>(&g_h3h[(size_t)gm * 32 + col0]) = st;
        }
    }
    __syncthreads();
    if (tid < 128) {
        int gm = m0 + tid;
        if (gm < M) {
            g_a2s[gm] = make_float2(s_ms[tid], s_lsm[tid]);
            g_a2d[gm] = make_float2(s_md[tid], s_ldm[tid]);
        }
    }
}

// ---------------- layer-2 agg: warp/node, half gather ----------------
__global__ __launch_bounds__(256) void k_agg2(
    const float* __restrict__ bmu, const float* __restrict__ bls,
    float* __restrict__ out, int N)
{
    __shared__ float4 stage[8][32];
    int n = (blockIdx.x * blockDim.x + threadIdx.x) >> 5;
    int lane = threadIdx.x & 31;
    int w = threadIdx.x >> 5;
    if (n >= N) return;
    int start = g_rowptr[n];
    int deg = g_deg[n];
    float2 ad = g_a2d[n];
    float2 as = g_a2s[n];
    float wsm = __expf(leakyf(as.x + ad.x));
    float wsl = __expf(leakyf(as.y + ad.y));
    bool is_mu = lane < 16;
    int c = lane & 15;
    float wself = is_mu ? wsm : wsl;
    float den = wself;
    float acc = wself * __half2float(g_h3h[(size_t)n * 32 + lane]);
    for (int base = 0; base < deg; base += 32) {
        int i = base + lane;
        float4 st = make_float4(0.f, 0.f, 0.f, 0.f);
        if (i < deg) {
            int s = g_col[start + i];
            float2 a = g_a2s[s];
            st.x = __int_as_float(s);
            st.y = __expf(leakyf(a.x + ad.x));
            st.z = __expf(leakyf(a.y + ad.y));
        }
        stage[w][lane] = st;
        __syncwarp();
        int cnt = min(32, deg - base);
#pragma unroll 4
        for (int j = 0; j < cnt; j++) {
            float4 v = stage[w][j];
            int sj = __float_as_int(v.x);
            float ww = is_mu ? v.y : v.z;
            den += ww;
            acc += ww * __half2float(g_h3h[(size_t)sj * 32 + lane]);
        }
        __syncwarp();
    }
    float res = acc * (1.f / (den + 1e-16f)) + (is_mu ? bmu[c] : bls[c]);
    if (is_mu) out[(size_t)n * 16 + c] = res;
    else       out[(size_t)N * 16 + (size_t)n * 16 + c] = res;
}

// ---------------- launch ----------------
extern "C" void kernel_launch(void* const* d_in, const int* in_sizes, int n_in,
                              void* d_out, int out_size) {
    const float* x    = (const float*)d_in[0];
    const void*  ei   = d_in[1];
    const float* W1   = (const float*)d_in[2];
    const float* as1  = (const float*)d_in[3];
    const float* ad1  = (const float*)d_in[4];
    const float* b1   = (const float*)d_in[5];
    const float* Wmu  = (const float*)d_in[6];
    const float* asmu = (const float*)d_in[7];
    const float* admu = (const float*)d_in[8];
    const float* bmu  = (const float*)d_in[9];
    const float* Wls  = (const float*)d_in[10];
    const float* asls = (const float*)d_in[11];
    const float* adls = (const float*)d_in[12];
    const float* bls  = (const float*)d_in[13];
    int N = in_sizes[0] / 128;
    int E = in_sizes[1] / 2;
    float* out = (float*)d_out;

    static cudaStream_t s2 = nullptr;
    static cudaEvent_t evF = nullptr, evJ = nullptr;
    if (s2 == nullptr) {
        cudaStreamCreateWithFlags(&s2, cudaStreamNonBlocking);
        cudaEventCreateWithFlags(&evF, cudaEventDisableTiming);
        cudaEventCreateWithFlags(&evJ, cudaEventDisableTiming);
    }

    const int TB = 256;
    int nb = (N + 1023) / 1024;

    cudaEventRecord(evF, 0);
    cudaStreamWaitEvent(s2, evF, 0);

    k_init<<<(N + TB - 1) / TB, TB>>>(ei, E, N);               // idx0
    k_hist<<<(E + 511) / 512, 512>>>(ei, E);                   // idx1
    k_scan1<<<nb, 1024>>>(N);                                  // idx2
    k_gemm1<<<(N + 127) / 128, 256, 0, s2>>>(x, W1, as1, ad1, N); // idx3 (profiled)
    k_scan23<<<nb, 1024>>>(N, nb);                             // idx4
    k_scatter<<<(E + 511) / 512, 512>>>(ei, E);                // idx5

    cudaEventRecord(evJ, s2);
    cudaStreamWaitEvent(0, evJ, 0);

    k_agg1<<<(N * 32 + TB - 1) / TB, TB>>>(b1, N);             // idx6
    k_gemm2<<<(N + 127) / 128, 256>>>(Wmu, Wls, asmu, admu, asls, adls, N); // idx7
    k_agg2<<<(N * 32 + TB - 1) / TB, TB>>>(bmu, bls, out, N);  // idx8
}